// round 9
// baseline (speedup 1.0000x reference)
#include <cuda_runtime.h>
#include <cstdint>

// Problem sizes (fixed by the dataset; bounds for static scratch)
static constexpr int NN = 50000;
static constexpr int EE = 800000;

// Scratch (device globals: allocation-free per harness rules)
__device__ __align__(16) float g_x[(long long)NN * 128];  // mlp output [N,128]
__device__ float4 g_h1[NN];        // per-node logits, conv1 (4 heads)
__device__ float4 g_h2[NN];        // per-node logits, conv2 (4 heads)
__device__ int    g_cnt[NN];       // per-src degree
__device__ int    g_off[NN + 1];   // CSR row offsets
__device__ int    g_cur[NN];       // scatter cursors
__device__ int    g_sdst[EE];      // dst sorted by src
__device__ float4 g_sv[EE];        // per-edge relu(h1[src]+h2[dst]) (4 heads)

// ---------------------------------------------------------------------------
// Kernel 1: X = feat @ W_mlp + b_mlp  (SGEMM, packed f32x2 FMA)
// BM=128, BN=128, BK=16, 256 threads, 8x8 micro-tile per thread
// ---------------------------------------------------------------------------
__global__ __launch_bounds__(256) void gemm_mlp_kernel(
    const float* __restrict__ A,     // feat [N,256]
    const float* __restrict__ B,     // W_mlp [256,128] row-major (K x N)
    const float* __restrict__ bias,  // [128]
    int N)
{
    __shared__ float As[16][128];  // transposed A tile: As[k][m]
    __shared__ float Bs[16][128];  // Bs[k][n]

    const int tid  = threadIdx.x;
    const int brow = blockIdx.x * 128;
    const int tcol = (tid & 15) * 8;   // 0..120
    const int trow = (tid >> 4) * 8;   // 0..120

    unsigned long long acc2[8][4];
#pragma unroll
    for (int i = 0; i < 8; i++)
#pragma unroll
        for (int j = 0; j < 4; j++) acc2[i][j] = 0ull;

    for (int k0 = 0; k0 < 256; k0 += 16) {
#pragma unroll
        for (int i = 0; i < 2; i++) {
            int idx = tid * 2 + i;          // 0..511
            int r   = idx >> 2;             // 0..127
            int c4  = (idx & 3) * 4;        // 0,4,8,12
            int gr  = brow + r;
            float4 v = make_float4(0.f, 0.f, 0.f, 0.f);
            if (gr < N) v = *(const float4*)(A + (long long)gr * 256 + k0 + c4);
            As[c4 + 0][r] = v.x;
            As[c4 + 1][r] = v.y;
            As[c4 + 2][r] = v.z;
            As[c4 + 3][r] = v.w;
        }
#pragma unroll
        for (int i = 0; i < 2; i++) {
            int idx = tid * 2 + i;          // 0..511
            int r   = idx >> 5;             // 0..15
            int c4  = (idx & 31) * 4;       // 0..124
            *(float4*)&Bs[r][c4] = *(const float4*)(B + (long long)(k0 + r) * 128 + c4);
        }
        __syncthreads();

#pragma unroll
        for (int k = 0; k < 16; k++) {
            unsigned long long bn2[4];
            {
                float4 b0 = *(const float4*)&Bs[k][tcol];
                float4 b1 = *(const float4*)&Bs[k][tcol + 4];
                float2 p;
                p = make_float2(b0.x, b0.y); bn2[0] = *reinterpret_cast<unsigned long long*>(&p);
                p = make_float2(b0.z, b0.w); bn2[1] = *reinterpret_cast<unsigned long long*>(&p);
                p = make_float2(b1.x, b1.y); bn2[2] = *reinterpret_cast<unsigned long long*>(&p);
                p = make_float2(b1.z, b1.w); bn2[3] = *reinterpret_cast<unsigned long long*>(&p);
            }
            float am[8];
            {
                float4 a0 = *(const float4*)&As[k][trow];
                float4 a1 = *(const float4*)&As[k][trow + 4];
                am[0] = a0.x; am[1] = a0.y; am[2] = a0.z; am[3] = a0.w;
                am[4] = a1.x; am[5] = a1.y; am[6] = a1.z; am[7] = a1.w;
            }
#pragma unroll
            for (int i = 0; i < 8; i++) {
                unsigned long long am2;
                asm("mov.b64 %0, {%1, %1};" : "=l"(am2) : "f"(am[i]));
#pragma unroll
                for (int j = 0; j < 4; j++) {
                    asm("fma.rn.f32x2 %0, %1, %2, %3;"
                        : "=l"(acc2[i][j])
                        : "l"(am2), "l"(bn2[j]), "l"(acc2[i][j]));
                }
            }
        }
        __syncthreads();
    }

#pragma unroll
    for (int i = 0; i < 8; i++) {
        int gr = brow + trow + i;
        if (gr < N) {
#pragma unroll
            for (int j = 0; j < 2; j++) {
                float2 p0 = *reinterpret_cast<float2*>(&acc2[i][2 * j + 0]);
                float2 p1 = *reinterpret_cast<float2*>(&acc2[i][2 * j + 1]);
                float4 v;
                v.x = p0.x + bias[tcol + 4 * j + 0];
                v.y = p0.y + bias[tcol + 4 * j + 1];
                v.z = p1.x + bias[tcol + 4 * j + 2];
                v.w = p1.y + bias[tcol + 4 * j + 3];
                *(float4*)(g_x + (long long)gr * 128 + tcol + 4 * j) = v;
            }
        }
    }
}

// ---------------------------------------------------------------------------
// Kernel 2: h1 = feat @ W1^T + b1, h2 = feat @ W2^T + b2   (one warp / node)
// ---------------------------------------------------------------------------
__global__ __launch_bounds__(256) void h_kernel(
    const float* __restrict__ feat,
    const float* __restrict__ W1, const float* __restrict__ b1,
    const float* __restrict__ W2, const float* __restrict__ b2,
    int N)
{
    int warp = (blockIdx.x * blockDim.x + threadIdx.x) >> 5;
    if (warp >= N) return;
    int lane = threadIdx.x & 31;

    float a[4] = {0.f, 0.f, 0.f, 0.f};
    float b[4] = {0.f, 0.f, 0.f, 0.f};
    const float* frow = feat + (long long)warp * 256;
#pragma unroll
    for (int kk = 0; kk < 8; kk++) {
        int k   = lane + kk * 32;
        float f = frow[k];
#pragma unroll
        for (int j = 0; j < 4; j++) {
            a[j] = fmaf(f, __ldg(W1 + j * 256 + k), a[j]);
            b[j] = fmaf(f, __ldg(W2 + j * 256 + k), b[j]);
        }
    }
#pragma unroll
    for (int off = 16; off; off >>= 1) {
#pragma unroll
        for (int j = 0; j < 4; j++) {
            a[j] += __shfl_xor_sync(0xFFFFFFFFu, a[j], off);
            b[j] += __shfl_xor_sync(0xFFFFFFFFu, b[j], off);
        }
    }
    if (lane == 0) {
        g_h1[warp] = make_float4(a[0] + b1[0], a[1] + b1[1], a[2] + b1[2], a[3] + b1[3]);
        g_h2[warp] = make_float4(b[0] + b2[0], b[1] + b2[1], b[2] + b2[2], b[3] + b2[3]);
    }
}

// ---------------------------------------------------------------------------
// CSR build: zero counts, count degrees, scan, then scatter (dst + precomputed v)
// ---------------------------------------------------------------------------
__global__ void zero_cnt_kernel(int N)
{
    int i = blockIdx.x * blockDim.x + threadIdx.x;
    if (i < N) g_cnt[i] = 0;
}

__global__ void count_kernel(const int* __restrict__ ei, int E)
{
    int e = blockIdx.x * blockDim.x + threadIdx.x;
    if (e < E) atomicAdd(&g_cnt[ei[e]], 1);
}

__global__ __launch_bounds__(1024) void scan_kernel(int N)
{
    __shared__ int warp_sums[32];
    __shared__ int s_carry;
    const int tid = threadIdx.x, lane = tid & 31, wid = tid >> 5;
    if (tid == 0) s_carry = 0;
    __syncthreads();

    for (int base = 0; base < N; base += 1024) {
        int i = base + tid;
        int v = (i < N) ? g_cnt[i] : 0;
        int x = v;
#pragma unroll
        for (int o = 1; o < 32; o <<= 1) {
            int y = __shfl_up_sync(0xFFFFFFFFu, x, o);
            if (lane >= o) x += y;
        }
        if (lane == 31) warp_sums[wid] = x;
        __syncthreads();
        if (wid == 0) {
            int s = warp_sums[lane];
#pragma unroll
            for (int o = 1; o < 32; o <<= 1) {
                int y = __shfl_up_sync(0xFFFFFFFFu, s, o);
                if (lane >= o) s += y;
            }
            warp_sums[lane] = s;
        }
        __syncthreads();
        int warp_off = (wid == 0) ? 0 : warp_sums[wid - 1];
        int excl = s_carry + warp_off + x - v;
        if (i < N) { g_off[i] = excl; g_cur[i] = excl; }
        int chunk_total = warp_sums[31];
        __syncthreads();
        if (tid == 0) s_carry += chunk_total;
        __syncthreads();
    }
    if (tid == 0) g_off[N] = s_carry;
}

// Scatter + precompute per-edge attention v = relu(h1[src] + h2[dst])
__global__ void scatter_v_kernel(const int* __restrict__ ei, int E)
{
    int e = blockIdx.x * blockDim.x + threadIdx.x;
    if (e < E) {
        int s = ei[e];
        int d = ei[E + e];
        int pos = atomicAdd(&g_cur[s], 1);
        float4 a = g_h1[s];
        float4 b = g_h2[d];
        float4 v;
        v.x = fmaxf(a.x + b.x, 0.f);
        v.y = fmaxf(a.y + b.y, 0.f);
        v.z = fmaxf(a.z + b.z, 0.f);
        v.w = fmaxf(a.w + b.w, 0.f);
        g_sdst[pos] = d;
        g_sv[pos]   = v;
    }
}

// ---------------------------------------------------------------------------
// Kernel 4: aggregate.  One warp per node, no atomics, prepacked (dst, v).
//   out[n][h*32+f] = sum_{e: src=n} v[e][h] * x[dst][h*32+f] + eps * x[n][..]
// Inner chain is now a single gather hop: (dst, v) stream -> x.
// ---------------------------------------------------------------------------
__device__ __forceinline__ float head_sel4(const float4 h, int head) {
    return (head & 2) ? ((head & 1) ? h.w : h.z)
                      : ((head & 1) ? h.y : h.x);
}

__global__ __launch_bounds__(256) void agg_kernel(
    const float* __restrict__ eps,
    float* __restrict__ OUT,
    int N)
{
    int node = (blockIdx.x * blockDim.x + threadIdx.x) >> 5;
    if (node >= N) return;
    int lane = threadIdx.x & 31;
    int head = lane >> 3;           // 4 heads, 8 lanes each
    int j    = lane * 4;            // feature offset (float4)

    int i   = g_off[node];
    int end = g_off[node + 1];

    float4 acc0 = make_float4(0.f, 0.f, 0.f, 0.f);
    float4 acc1 = make_float4(0.f, 0.f, 0.f, 0.f);

    // 4-edge batches: v known up-front, x gathers issue back-to-back (MLP=4)
    for (; i + 4 <= end; i += 4) {
        int   dd[4];
        float vh[4];
#pragma unroll
        for (int k = 0; k < 4; k++) {
            dd[k] = __ldg(&g_sdst[i + k]);
            float4 vv = g_sv[i + k];     // broadcast across warp
            vh[k] = head_sel4(vv, head);
        }
#pragma unroll
        for (int k = 0; k < 4; k++) {
            if (vh[k] > 0.f) {
                float4 xv = *(const float4*)(g_x + (long long)dd[k] * 128 + j);
                float4& a = (k & 1) ? acc1 : acc0;
                a.x = fmaf(vh[k], xv.x, a.x);
                a.y = fmaf(vh[k], xv.y, a.y);
                a.z = fmaf(vh[k], xv.z, a.z);
                a.w = fmaf(vh[k], xv.w, a.w);
            }
        }
    }
    for (; i < end; i++) {   // tail
        int d = __ldg(&g_sdst[i]);
        float vh = head_sel4(g_sv[i], head);
        if (vh > 0.f) {
            float4 xv = *(const float4*)(g_x + (long long)d * 128 + j);
            acc0.x = fmaf(vh, xv.x, acc0.x);
            acc0.y = fmaf(vh, xv.y, acc0.y);
            acc0.z = fmaf(vh, xv.z, acc0.z);
            acc0.w = fmaf(vh, xv.w, acc0.w);
        }
    }

    float e0 = eps[0];
    float4 xs = *(const float4*)(g_x + (long long)node * 128 + j);
    float4 o;
    o.x = fmaf(e0, xs.x, acc0.x + acc1.x);
    o.y = fmaf(e0, xs.y, acc0.y + acc1.y);
    o.z = fmaf(e0, xs.z, acc0.z + acc1.z);
    o.w = fmaf(e0, xs.w, acc0.w + acc1.w);
    *(float4*)(OUT + (long long)node * 128 + j) = o;
}

// ---------------------------------------------------------------------------
extern "C" void kernel_launch(void* const* d_in, const int* in_sizes, int n_in,
                              void* d_out, int out_size)
{
    const float* feat  = (const float*)d_in[0];
    const int*   ei    = (const int*)d_in[1];
    const float* W_mlp = (const float*)d_in[2];
    const float* b_mlp = (const float*)d_in[3];
    const float* W1    = (const float*)d_in[4];
    const float* b1    = (const float*)d_in[5];
    const float* W2    = (const float*)d_in[6];
    const float* b2    = (const float*)d_in[7];
    const float* eps   = (const float*)d_in[8];

    const int N = in_sizes[0] / 256;
    const int E = in_sizes[1] / 2;
    float* out = (float*)d_out;

    // One-time side stream + fork/join events (host objects, no device mem)
    static cudaStream_t s_side = nullptr;
    static cudaEvent_t  ev_fork = nullptr, ev_join = nullptr;
    if (!s_side) {
        cudaStreamCreateWithFlags(&s_side, cudaStreamNonBlocking);
        cudaEventCreateWithFlags(&ev_fork, cudaEventDisableTiming);
        cudaEventCreateWithFlags(&ev_join, cudaEventDisableTiming);
    }

    // Fork: CSR build + h + v-precompute on side stream, under the GEMM.
    cudaEventRecord(ev_fork, 0);
    cudaStreamWaitEvent(s_side, ev_fork, 0);

    zero_cnt_kernel<<<(N + 511) / 512, 512, 0, s_side>>>(N);
    count_kernel<<<(E + 255) / 256, 256, 0, s_side>>>(ei, E);
    scan_kernel<<<1, 1024, 0, s_side>>>(N);
    h_kernel<<<(N + 7) / 8, 256, 0, s_side>>>(feat, W1, b1, W2, b2, N);
    scatter_v_kernel<<<(E + 255) / 256, 256, 0, s_side>>>(ei, E);
    cudaEventRecord(ev_join, s_side);

    // Dense chain on capture (NULL) stream.
    gemm_mlp_kernel<<<(N + 127) / 128, 256>>>(feat, W_mlp, b_mlp, N);

    // Join, then atomic-free aggregation + epilogue.
    cudaStreamWaitEvent(0, ev_join, 0);
    agg_kernel<<<(N + 7) / 8, 256>>>(eps, out, N);
}

// round 10
// speedup vs baseline: 1.0338x; 1.0338x over previous
#include <cuda_runtime.h>
#include <cstdint>

// Problem sizes (fixed by the dataset; bounds for static scratch)
static constexpr int NN = 50000;
static constexpr int EE = 800000;

// Scratch (device globals: allocation-free per harness rules)
__device__ __align__(16) float g_x[(long long)NN * 128];  // mlp output [N,128]
__device__ float4 g_h1[NN];        // per-node logits, conv1 (4 heads)
__device__ float4 g_h2[NN];        // per-node logits, conv2 (4 heads)
__device__ int    g_cnt[NN];       // per-src degree
__device__ int    g_off[NN + 1];   // CSR row offsets
__device__ int    g_cur[NN];       // scatter cursors
__device__ int    g_sdst[EE];      // dst sorted by src

// ---------------------------------------------------------------------------
// Kernel 1: X = feat @ W_mlp + b_mlp  (SGEMM, packed f32x2 FMA)
// BM=128, BN=128, BK=16, 256 threads, 8x8 micro-tile per thread
// ---------------------------------------------------------------------------
__global__ __launch_bounds__(256) void gemm_mlp_kernel(
    const float* __restrict__ A,     // feat [N,256]
    const float* __restrict__ B,     // W_mlp [256,128] row-major (K x N)
    const float* __restrict__ bias,  // [128]
    int N)
{
    __shared__ float As[16][128];  // transposed A tile: As[k][m]
    __shared__ float Bs[16][128];  // Bs[k][n]

    const int tid  = threadIdx.x;
    const int brow = blockIdx.x * 128;
    const int tcol = (tid & 15) * 8;   // 0..120
    const int trow = (tid >> 4) * 8;   // 0..120

    unsigned long long acc2[8][4];
#pragma unroll
    for (int i = 0; i < 8; i++)
#pragma unroll
        for (int j = 0; j < 4; j++) acc2[i][j] = 0ull;

    for (int k0 = 0; k0 < 256; k0 += 16) {
#pragma unroll
        for (int i = 0; i < 2; i++) {
            int idx = tid * 2 + i;          // 0..511
            int r   = idx >> 2;             // 0..127
            int c4  = (idx & 3) * 4;        // 0,4,8,12
            int gr  = brow + r;
            float4 v = make_float4(0.f, 0.f, 0.f, 0.f);
            if (gr < N) v = *(const float4*)(A + (long long)gr * 256 + k0 + c4);
            As[c4 + 0][r] = v.x;
            As[c4 + 1][r] = v.y;
            As[c4 + 2][r] = v.z;
            As[c4 + 3][r] = v.w;
        }
#pragma unroll
        for (int i = 0; i < 2; i++) {
            int idx = tid * 2 + i;          // 0..511
            int r   = idx >> 5;             // 0..15
            int c4  = (idx & 31) * 4;       // 0..124
            *(float4*)&Bs[r][c4] = *(const float4*)(B + (long long)(k0 + r) * 128 + c4);
        }
        __syncthreads();

#pragma unroll
        for (int k = 0; k < 16; k++) {
            unsigned long long bn2[4];
            {
                float4 b0 = *(const float4*)&Bs[k][tcol];
                float4 b1 = *(const float4*)&Bs[k][tcol + 4];
                float2 p;
                p = make_float2(b0.x, b0.y); bn2[0] = *reinterpret_cast<unsigned long long*>(&p);
                p = make_float2(b0.z, b0.w); bn2[1] = *reinterpret_cast<unsigned long long*>(&p);
                p = make_float2(b1.x, b1.y); bn2[2] = *reinterpret_cast<unsigned long long*>(&p);
                p = make_float2(b1.z, b1.w); bn2[3] = *reinterpret_cast<unsigned long long*>(&p);
            }
            float am[8];
            {
                float4 a0 = *(const float4*)&As[k][trow];
                float4 a1 = *(const float4*)&As[k][trow + 4];
                am[0] = a0.x; am[1] = a0.y; am[2] = a0.z; am[3] = a0.w;
                am[4] = a1.x; am[5] = a1.y; am[6] = a1.z; am[7] = a1.w;
            }
#pragma unroll
            for (int i = 0; i < 8; i++) {
                unsigned long long am2;
                asm("mov.b64 %0, {%1, %1};" : "=l"(am2) : "f"(am[i]));
#pragma unroll
                for (int j = 0; j < 4; j++) {
                    asm("fma.rn.f32x2 %0, %1, %2, %3;"
                        : "=l"(acc2[i][j])
                        : "l"(am2), "l"(bn2[j]), "l"(acc2[i][j]));
                }
            }
        }
        __syncthreads();
    }

#pragma unroll
    for (int i = 0; i < 8; i++) {
        int gr = brow + trow + i;
        if (gr < N) {
#pragma unroll
            for (int j = 0; j < 2; j++) {
                float2 p0 = *reinterpret_cast<float2*>(&acc2[i][2 * j + 0]);
                float2 p1 = *reinterpret_cast<float2*>(&acc2[i][2 * j + 1]);
                float4 v;
                v.x = p0.x + bias[tcol + 4 * j + 0];
                v.y = p0.y + bias[tcol + 4 * j + 1];
                v.z = p1.x + bias[tcol + 4 * j + 2];
                v.w = p1.y + bias[tcol + 4 * j + 3];
                *(float4*)(g_x + (long long)gr * 128 + tcol + 4 * j) = v;
            }
        }
    }
}

// ---------------------------------------------------------------------------
// Kernel 2: h1 = feat @ W1^T + b1, h2 = feat @ W2^T + b2   (one warp / node)
// ---------------------------------------------------------------------------
__global__ __launch_bounds__(256) void h_kernel(
    const float* __restrict__ feat,
    const float* __restrict__ W1, const float* __restrict__ b1,
    const float* __restrict__ W2, const float* __restrict__ b2,
    int N)
{
    int warp = (blockIdx.x * blockDim.x + threadIdx.x) >> 5;
    if (warp >= N) return;
    int lane = threadIdx.x & 31;

    float a[4] = {0.f, 0.f, 0.f, 0.f};
    float b[4] = {0.f, 0.f, 0.f, 0.f};
    const float* frow = feat + (long long)warp * 256;
#pragma unroll
    for (int kk = 0; kk < 8; kk++) {
        int k   = lane + kk * 32;
        float f = frow[k];
#pragma unroll
        for (int j = 0; j < 4; j++) {
            a[j] = fmaf(f, __ldg(W1 + j * 256 + k), a[j]);
            b[j] = fmaf(f, __ldg(W2 + j * 256 + k), b[j]);
        }
    }
#pragma unroll
    for (int off = 16; off; off >>= 1) {
#pragma unroll
        for (int j = 0; j < 4; j++) {
            a[j] += __shfl_xor_sync(0xFFFFFFFFu, a[j], off);
            b[j] += __shfl_xor_sync(0xFFFFFFFFu, b[j], off);
        }
    }
    if (lane == 0) {
        g_h1[warp] = make_float4(a[0] + b1[0], a[1] + b1[1], a[2] + b1[2], a[3] + b1[3]);
        g_h2[warp] = make_float4(b[0] + b2[0], b[1] + b2[1], b[2] + b2[2], b[3] + b2[3]);
    }
}

// ---------------------------------------------------------------------------
// CSR build: zero counts, count degrees, scan, scatter dst by src
// ---------------------------------------------------------------------------
__global__ void zero_cnt_kernel(int N)
{
    int i = blockIdx.x * blockDim.x + threadIdx.x;
    if (i < N) g_cnt[i] = 0;
}

__global__ void count_kernel(const int* __restrict__ ei, int E)
{
    int e = blockIdx.x * blockDim.x + threadIdx.x;
    if (e < E) atomicAdd(&g_cnt[ei[e]], 1);
}

__global__ __launch_bounds__(1024) void scan_kernel(int N)
{
    __shared__ int warp_sums[32];
    __shared__ int s_carry;
    const int tid = threadIdx.x, lane = tid & 31, wid = tid >> 5;
    if (tid == 0) s_carry = 0;
    __syncthreads();

    for (int base = 0; base < N; base += 1024) {
        int i = base + tid;
        int v = (i < N) ? g_cnt[i] : 0;
        int x = v;
#pragma unroll
        for (int o = 1; o < 32; o <<= 1) {
            int y = __shfl_up_sync(0xFFFFFFFFu, x, o);
            if (lane >= o) x += y;
        }
        if (lane == 31) warp_sums[wid] = x;
        __syncthreads();
        if (wid == 0) {
            int s = warp_sums[lane];
#pragma unroll
            for (int o = 1; o < 32; o <<= 1) {
                int y = __shfl_up_sync(0xFFFFFFFFu, s, o);
                if (lane >= o) s += y;
            }
            warp_sums[lane] = s;
        }
        __syncthreads();
        int warp_off = (wid == 0) ? 0 : warp_sums[wid - 1];
        int excl = s_carry + warp_off + x - v;
        if (i < N) { g_off[i] = excl; g_cur[i] = excl; }
        int chunk_total = warp_sums[31];
        __syncthreads();
        if (tid == 0) s_carry += chunk_total;
        __syncthreads();
    }
    if (tid == 0) g_off[N] = s_carry;
}

__global__ void scatter_kernel(const int* __restrict__ ei, int E)
{
    int e = blockIdx.x * blockDim.x + threadIdx.x;
    if (e < E) {
        int s = ei[e];
        int d = ei[E + e];
        int pos = atomicAdd(&g_cur[s], 1);
        g_sdst[pos] = d;
    }
}

// ---------------------------------------------------------------------------
// Kernel 4: aggregate.  TWO warps per node (edge-range split), no atomics.
//   Each warp handles half the node's edge list with the round-4 2-edge ILP
//   loop; partial sums combined through shared memory.
// ---------------------------------------------------------------------------
__global__ __launch_bounds__(256) void agg_kernel(
    const float* __restrict__ eps,
    float* __restrict__ OUT,
    int N)
{
    __shared__ float4 s_part[4][32];   // partial acc from the odd warp of each pair

    const int tid   = threadIdx.x;
    const int wid   = tid >> 5;        // 0..7
    const int lane  = tid & 31;
    const int nloc  = wid >> 1;        // node slot in block: 0..3
    const int half  = wid & 1;         // which half of the edge list
    const int node  = blockIdx.x * 4 + nloc;
    const int head  = lane >> 3;       // 4 heads, 8 lanes each
    const int j     = lane * 4;        // feature offset (float4)

    float4 acc0 = make_float4(0.f, 0.f, 0.f, 0.f);
    float4 acc1 = make_float4(0.f, 0.f, 0.f, 0.f);

    if (node < N) {
        float4 ha = g_h1[node];
        float ha_h = (head < 2) ? (head == 0 ? ha.x : ha.y)
                                : (head == 2 ? ha.z : ha.w);

        int beg  = g_off[node];
        int end  = g_off[node + 1];
        int len  = end - beg;
        int h0   = (len + 1) >> 1;            // ceil(len/2)
        int lo   = beg + half * h0;
        int hi   = half ? end : beg + h0;

        int i = lo;
        for (; i + 2 <= hi; i += 2) {
            int d0 = __ldg(&g_sdst[i]);
            int d1 = __ldg(&g_sdst[i + 1]);
            float4 hb0 = g_h2[d0];
            float4 hb1 = g_h2[d1];
            float v0 = ha_h + ((head < 2) ? (head == 0 ? hb0.x : hb0.y)
                                          : (head == 2 ? hb0.z : hb0.w));
            float v1 = ha_h + ((head < 2) ? (head == 0 ? hb1.x : hb1.y)
                                          : (head == 2 ? hb1.z : hb1.w));
            if (v0 > 0.f) {
                float4 xv = *(const float4*)(g_x + (long long)d0 * 128 + j);
                acc0.x = fmaf(v0, xv.x, acc0.x);
                acc0.y = fmaf(v0, xv.y, acc0.y);
                acc0.z = fmaf(v0, xv.z, acc0.z);
                acc0.w = fmaf(v0, xv.w, acc0.w);
            }
            if (v1 > 0.f) {
                float4 xv = *(const float4*)(g_x + (long long)d1 * 128 + j);
                acc1.x = fmaf(v1, xv.x, acc1.x);
                acc1.y = fmaf(v1, xv.y, acc1.y);
                acc1.z = fmaf(v1, xv.z, acc1.z);
                acc1.w = fmaf(v1, xv.w, acc1.w);
            }
        }
        if (i < hi) {  // tail edge of this half
            int d0 = __ldg(&g_sdst[i]);
            float4 hb0 = g_h2[d0];
            float v0 = ha_h + ((head < 2) ? (head == 0 ? hb0.x : hb0.y)
                                          : (head == 2 ? hb0.z : hb0.w));
            if (v0 > 0.f) {
                float4 xv = *(const float4*)(g_x + (long long)d0 * 128 + j);
                acc0.x = fmaf(v0, xv.x, acc0.x);
                acc0.y = fmaf(v0, xv.y, acc0.y);
                acc0.z = fmaf(v0, xv.z, acc0.z);
                acc0.w = fmaf(v0, xv.w, acc0.w);
            }
        }
    }

    // Combine halves: odd warp deposits, even warp finishes.
    if (half == 1) {
        float4 p;
        p.x = acc0.x + acc1.x;
        p.y = acc0.y + acc1.y;
        p.z = acc0.z + acc1.z;
        p.w = acc0.w + acc1.w;
        s_part[nloc][lane] = p;
    }
    __syncthreads();

    if (half == 0 && node < N) {
        float4 p = s_part[nloc][lane];
        float e0 = eps[0];
        float4 xs = *(const float4*)(g_x + (long long)node * 128 + j);
        float4 o;
        o.x = fmaf(e0, xs.x, (acc0.x + acc1.x) + p.x);
        o.y = fmaf(e0, xs.y, (acc0.y + acc1.y) + p.y);
        o.z = fmaf(e0, xs.z, (acc0.z + acc1.z) + p.z);
        o.w = fmaf(e0, xs.w, (acc0.w + acc1.w) + p.w);
        *(float4*)(OUT + (long long)node * 128 + j) = o;
    }
}

// ---------------------------------------------------------------------------
extern "C" void kernel_launch(void* const* d_in, const int* in_sizes, int n_in,
                              void* d_out, int out_size)
{
    const float* feat  = (const float*)d_in[0];
    const int*   ei    = (const int*)d_in[1];
    const float* W_mlp = (const float*)d_in[2];
    const float* b_mlp = (const float*)d_in[3];
    const float* W1    = (const float*)d_in[4];
    const float* b1    = (const float*)d_in[5];
    const float* W2    = (const float*)d_in[6];
    const float* b2    = (const float*)d_in[7];
    const float* eps   = (const float*)d_in[8];

    const int N = in_sizes[0] / 256;
    const int E = in_sizes[1] / 2;
    float* out = (float*)d_out;

    // One-time side stream + fork/join events (host objects, no device mem)
    static cudaStream_t s_side = nullptr;
    static cudaEvent_t  ev_fork = nullptr, ev_join = nullptr;
    if (!s_side) {
        cudaStreamCreateWithFlags(&s_side, cudaStreamNonBlocking);
        cudaEventCreateWithFlags(&ev_fork, cudaEventDisableTiming);
        cudaEventCreateWithFlags(&ev_join, cudaEventDisableTiming);
    }

    // Fork: CSR build on side stream, hidden under the GEMM.
    cudaEventRecord(ev_fork, 0);
    cudaStreamWaitEvent(s_side, ev_fork, 0);

    zero_cnt_kernel<<<(N + 511) / 512, 512, 0, s_side>>>(N);
    count_kernel<<<(E + 255) / 256, 256, 0, s_side>>>(ei, E);
    scan_kernel<<<1, 1024, 0, s_side>>>(N);
    scatter_kernel<<<(E + 255) / 256, 256, 0, s_side>>>(ei, E);
    cudaEventRecord(ev_join, s_side);

    // Dense chain on capture (NULL) stream.
    gemm_mlp_kernel<<<(N + 127) / 128, 256>>>(feat, W_mlp, b_mlp, N);
    h_kernel<<<(N + 7) / 8, 256>>>(feat, W1, b1, W2, b2, N);

    // Join, then atomic-free aggregation + epilogue (2 warps / node).
    cudaStreamWaitEvent(0, ev_join, 0);
    agg_kernel<<<(N + 3) / 4, 256>>>(eps, out, N);
}